// round 3
// baseline (speedup 1.0000x reference)
#include <cuda_runtime.h>
#include <math.h>

#define Bb 4
#define Ss 512
#define Hh 768
#define Dd 24
#define Mm 96
#define OH 768
#define H3 2304
#define NROWS (Bb*Ss)   // 2048

typedef unsigned long long ull;

// ---- scratch ----
__device__ float g_Zj[NROWS*Dd];
__device__ float g_Zi[NROWS*Dd];
__device__ float g_Aj[NROWS*Mm];
__device__ float g_Bi[NROWS*Mm];
__device__ float g_probs[(long)Bb*Ss*Ss];
__device__ float g_ctx[(long)NROWS*Hh];
__device__ float g_hid2[(long)NROWS*OH];
__device__ float g_part1[2L*NROWS*OH];
__device__ float g_part2[2L*NROWS*Hh];

// ---- packed f32x2 helpers ----
__device__ __forceinline__ ull pack2(float lo, float hi){
    ull r; asm("mov.b64 %0, {%1, %2};" : "=l"(r) : "f"(lo), "f"(hi)); return r;
}
__device__ __forceinline__ void unpack2(ull v, float& lo, float& hi){
    asm("mov.b64 {%0, %1}, %2;" : "=f"(lo), "=f"(hi) : "l"(v));
}
__device__ __forceinline__ ull fma2(ull a, ull b, ull c){
    ull d; asm("fma.rn.f32x2 %0, %1, %2, %3;" : "=l"(d) : "l"(a), "l"(b), "l"(c));
    return d;
}

// ============================================================
// K1: projections + rank-1 softmax-MLP terms
// ============================================================
__global__ __launch_bounds__(256) void proj_kernel(
    const float* __restrict__ Hj, const float* __restrict__ Hi,
    const float* __restrict__ pjw, const float* __restrict__ piw,
    const float* __restrict__ sw1)
{
    int r = blockIdx.x;
    __shared__ float shj[Hh], shi[Hh], szj[Dd], szi[Dd];
    int tid = threadIdx.x;
    for (int i = tid; i < Hh; i += 256){
        shj[i] = Hj[(long)r*Hh + i];
        shi[i] = Hi[(long)r*Hh + i];
    }
    __syncthreads();
    int o = tid >> 3, g = tid & 7;
    if (o < Dd){
        float pj = 0.f, pi = 0.f;
        for (int h = g; h < Hh; h += 8){
            pj += shj[h] * pjw[o*Hh + h];
            pi += shi[h] * piw[o*Hh + h];
        }
        #pragma unroll
        for (int d = 4; d > 0; d >>= 1){
            pj += __shfl_down_sync(0xffffffffu, pj, d, 8);
            pi += __shfl_down_sync(0xffffffffu, pi, d, 8);
        }
        if (g == 0){
            szj[o] = pj; szi[o] = pi;
            g_Zj[r*Dd + o] = pj; g_Zi[r*Dd + o] = pi;
        }
    }
    __syncthreads();
    if (tid < Mm){
        float a = 0.f, bsum = 0.f;
        #pragma unroll
        for (int d = 0; d < Dd; d++){
            a    += sw1[tid*96 +      d] * szj[d];
            bsum += sw1[tid*96 + 24 + d] * szi[d];
        }
        g_Aj[r*Mm + tid] = a;
        g_Bi[r*Mm + tid] = bsum;
    }
}

// ============================================================
// K2 v3: pairwise logits + masked softmax
// weights packed as ulonglong2 (2 d per LDS.128) -> 4 fma2/LDS
// ============================================================
__global__ __launch_bounds__(256) void pair_kernel(
    const float* __restrict__ sw1, const float* __restrict__ sb1,
    const float* __restrict__ sw2v, const float* __restrict__ sb2,
    const float* __restrict__ mask)
{
    int r = blockIdx.x;
    int b = r >> 9;
    __shared__ ulonglong2 sW[Mm][Dd/2];   // (wc,wd) pairs, 2 d per entry
    __shared__ float2 sCW[Mm];            // (sc, w2)
    __shared__ float szj[Dd];
    __shared__ float sred[8];
    int tid = threadIdx.x;

    for (int i = tid; i < Mm*(Dd/2); i += 256){
        int m = i / (Dd/2), p = i % (Dd/2);
        int d0 = 2*p, d1 = 2*p + 1;
        ulonglong2 w;
        w.x = pack2(sw1[m*96 + 48 + d0], sw1[m*96 + 72 + d0]);
        w.y = pack2(sw1[m*96 + 48 + d1], sw1[m*96 + 72 + d1]);
        sW[m][p] = w;
    }
    if (tid < Mm) sCW[tid] = make_float2(g_Aj[r*Mm + tid] + sb1[tid], sw2v[tid]);
    if (tid < Dd) szj[tid] = g_Zj[r*Dd + tid];
    __syncthreads();

    int t0 = tid, t1 = tid + 256;
    const float* zi0 = &g_Zi[(long)(b*Ss + t0)*Dd];
    const float* zi1 = &g_Zi[(long)(b*Ss + t1)*Dd];
    ull uv0[Dd], uv1[Dd];
    #pragma unroll
    for (int d = 0; d < Dd; d++){
        float zj = szj[d];
        float z0 = __ldg(&zi0[d]);
        float z1 = __ldg(&zi1[d]);
        uv0[d] = pack2(zj*z0, fabsf(zj - z0));
        uv1[d] = pack2(zj*z1, fabsf(zj - z1));
    }

    const float4* bi0 = (const float4*)&g_Bi[(long)(b*Ss + t0)*Mm];
    const float4* bi1 = (const float4*)&g_Bi[(long)(b*Ss + t1)*Mm];
    float logit0 = 0.f, logit1 = 0.f;

    #pragma unroll 1
    for (int mg = 0; mg < Mm/4; mg++){
        float4 bv0 = __ldg(&bi0[mg]);
        float4 bv1 = __ldg(&bi1[mg]);
        float bb0[4] = {bv0.x, bv0.y, bv0.z, bv0.w};
        float bb1[4] = {bv1.x, bv1.y, bv1.z, bv1.w};
        #pragma unroll
        for (int j = 0; j < 4; j++){
            int m = mg*4 + j;
            ull h0 = 0ull, h1 = 0ull;
            #pragma unroll
            for (int p = 0; p < Dd/2; p++){
                ulonglong2 w = sW[m][p];
                h0 = fma2(uv0[2*p  ], w.x, h0);
                h1 = fma2(uv1[2*p  ], w.x, h1);
                h0 = fma2(uv0[2*p+1], w.y, h0);
                h1 = fma2(uv1[2*p+1], w.y, h1);
            }
            float a0,c0,a1,c1;
            unpack2(h0, a0, c0);
            unpack2(h1, a1, c1);
            float2 cw = sCW[m];
            float hv0 = cw.x + bb0[j] + a0 + c0;
            float hv1 = cw.x + bb1[j] + a1 + c1;
            logit0 += cw.y * fmaxf(hv0, 0.f);
            logit1 += cw.y * fmaxf(hv1, 0.f);
        }
    }
    float lt0 = logit0 + sb2[0] + (1.f - mask[b*Ss + t0]) * (-3.402823466e38f);
    float lt1 = logit1 + sb2[0] + (1.f - mask[b*Ss + t1]) * (-3.402823466e38f);

    // block softmax over 512 logits
    float mx = fmaxf(lt0, lt1);
    #pragma unroll
    for (int d = 16; d > 0; d >>= 1)
        mx = fmaxf(mx, __shfl_xor_sync(0xffffffffu, mx, d));
    if ((tid & 31) == 0) sred[tid >> 5] = mx;
    __syncthreads();
    float bmax = sred[0];
    #pragma unroll
    for (int i = 1; i < 8; i++) bmax = fmaxf(bmax, sred[i]);

    float e0 = expf(lt0 - bmax);
    float e1 = expf(lt1 - bmax);
    float sm = e0 + e1;
    #pragma unroll
    for (int d = 16; d > 0; d >>= 1)
        sm += __shfl_xor_sync(0xffffffffu, sm, d);
    __syncthreads();
    if ((tid & 31) == 0) sred[tid >> 5] = sm;
    __syncthreads();
    float tot = 0.f;
    #pragma unroll
    for (int i = 0; i < 8; i++) tot += sred[i];
    float inv = 1.f / tot;

    g_probs[(long)r*Ss + t0] = e0 * inv;
    g_probs[(long)r*Ss + t1] = e1 * inv;
}

// ============================================================
// K3: tiled SGEMM — 128x128, 8x8/thread, f32x2, double-buffered.
// AFUSE: A is the virtual msg_in = [ctx | Hj | ctx*Hj] (row-major 2304)
// ============================================================
__device__ __forceinline__ float4 msgin_load(
    const float* __restrict__ ctxp, const float* __restrict__ Hjp,
    long rr, int kk)
{
    if (kk < Hh){
        return *(const float4*)&ctxp[rr*Hh + kk];
    } else if (kk < 2*Hh){
        return *(const float4*)&Hjp[rr*Hh + (kk - Hh)];
    } else {
        int c = kk - 2*Hh;
        float4 cv = *(const float4*)&ctxp[rr*Hh + c];
        float4 hv = *(const float4*)&Hjp[rr*Hh + c];
        return make_float4(cv.x*hv.x, cv.y*hv.y, cv.z*hv.z, cv.w*hv.w);
    }
}

template<bool TRANSB, bool SPLITK, int EPI, bool AFUSE>
__global__ __launch_bounds__(256) void gemm2_kernel(
    const float* __restrict__ A, const float* __restrict__ Bm,
    float* __restrict__ C, int N, int ldA, int ldB, int kcnt,
    long strideA, long strideB, long strideC,
    const float* __restrict__ bias, const float* __restrict__ scale_ptr,
    const float* __restrict__ ctxp, const float* __restrict__ Hjp)
{
    __shared__ float As[2][8][132];
    __shared__ float Bs[2][8][132];
    int tid = threadIdx.x;
    if (!AFUSE) A += (long)blockIdx.z * strideA;
    Bm += (long)blockIdx.z * strideB;
    C  += (long)blockIdx.z * strideC;
    int k0 = SPLITK ? blockIdx.z * kcnt : 0;
    int row0 = blockIdx.y * 128, col0 = blockIdx.x * 128;
    int lr = tid >> 1, lk = (tid & 1) * 4;
    int nk = tid >> 5, nc = (tid & 31) * 4;
    int tx = tid & 15, ty = tid >> 4;

    long arow = row0 + lr;
    int kk = k0 + lk;
    const float* Aptr = A + arow*ldA + kk;
    const float* Bptr = TRANSB ? (Bm + (long)(col0 + lr)*ldB + k0 + lk)
                               : (Bm + (long)(k0 + nk)*ldB + col0 + nc);

    float4 av = AFUSE ? msgin_load(ctxp, Hjp, arow, kk) : *(const float4*)Aptr;
    float4 bv = *(const float4*)Bptr;

    ull acc[8][4];
    #pragma unroll
    for (int i = 0; i < 8; i++)
        #pragma unroll
        for (int j = 0; j < 4; j++) acc[i][j] = 0ull;

    int nslices = kcnt >> 3;
    #pragma unroll 1
    for (int s = 0; s < nslices; s++){
        int cur = s & 1;
        As[cur][lk+0][lr] = av.x; As[cur][lk+1][lr] = av.y;
        As[cur][lk+2][lr] = av.z; As[cur][lk+3][lr] = av.w;
        if (TRANSB){
            Bs[cur][lk+0][lr] = bv.x; Bs[cur][lk+1][lr] = bv.y;
            Bs[cur][lk+2][lr] = bv.z; Bs[cur][lk+3][lr] = bv.w;
        } else {
            *(float4*)&Bs[cur][nk][nc] = bv;
        }
        __syncthreads();
        if (s + 1 < nslices){
            kk += 8;
            if (AFUSE){
                av = msgin_load(ctxp, Hjp, arow, kk);
            } else {
                Aptr += 8;
                av = *(const float4*)Aptr;
            }
            if (TRANSB){ Bptr += 8; }
            else       { Bptr += 8L * ldB; }
            bv = *(const float4*)Bptr;
        }
        #pragma unroll
        for (int k = 0; k < 8; k++){
            float4 a0 = *(const float4*)&As[cur][k][ty*8];
            float4 a1 = *(const float4*)&As[cur][k][ty*8 + 4];
            float4 b0 = *(const float4*)&Bs[cur][k][tx*8];
            float4 b1 = *(const float4*)&Bs[cur][k][tx*8 + 4];
            ull bp[4] = {pack2(b0.x,b0.y), pack2(b0.z,b0.w),
                         pack2(b1.x,b1.y), pack2(b1.z,b1.w)};
            float aa[8] = {a0.x,a0.y,a0.z,a0.w,a1.x,a1.y,a1.z,a1.w};
            #pragma unroll
            for (int i = 0; i < 8; i++){
                ull ai = pack2(aa[i], aa[i]);
                #pragma unroll
                for (int j = 0; j < 4; j++)
                    acc[i][j] = fma2(ai, bp[j], acc[i][j]);
            }
        }
        __syncthreads();
    }

    float sc = (EPI == 2) ? __ldg(scale_ptr) : 1.f;
    #pragma unroll
    for (int i = 0; i < 8; i++){
        int row = row0 + ty*8 + i;
        float cv[8];
        #pragma unroll
        for (int j = 0; j < 4; j++) unpack2(acc[i][j], cv[2*j], cv[2*j+1]);
        #pragma unroll
        for (int j = 0; j < 8; j++){
            int col = col0 + tx*8 + j;
            float v = cv[j];
            if (EPI >= 1) v += bias[col];
            if (EPI == 1) v = fmaxf(v, 0.f);
            if (EPI == 2) v *= sc;
            C[(long)row*N + col] = v;
        }
    }
}

// ============================================================
// split-K reduce + epilogue (vectorized float4)
// ============================================================
template<bool RELU, bool SCALE>
__global__ __launch_bounds__(256) void reduce_kernel(
    const float* __restrict__ p, float* __restrict__ out,
    const float* __restrict__ bias, const float* __restrict__ scale_ptr,
    int N, long total)
{
    long i4 = ((long)blockIdx.x * 256 + threadIdx.x) * 4;
    if (i4 >= total) return;
    int col = (int)(i4 % N);
    float4 a = *(const float4*)&p[i4];
    float4 b = *(const float4*)&p[total + i4];
    float4 bi = *(const float4*)&bias[col];
    float sc = SCALE ? __ldg(scale_ptr) : 1.f;
    float4 o;
    o.x = a.x + b.x + bi.x; o.y = a.y + b.y + bi.y;
    o.z = a.z + b.z + bi.z; o.w = a.w + b.w + bi.w;
    if (RELU){ o.x=fmaxf(o.x,0.f); o.y=fmaxf(o.y,0.f); o.z=fmaxf(o.z,0.f); o.w=fmaxf(o.w,0.f); }
    if (SCALE){ o.x*=sc; o.y*=sc; o.z*=sc; o.w*=sc; }
    *(float4*)&out[i4] = o;
}

// ============================================================
extern "C" void kernel_launch(void* const* d_in, const int* in_sizes, int n_in,
                              void* d_out, int out_size)
{
    const float* Hj   = (const float*)d_in[0];
    const float* Hi   = (const float*)d_in[1];
    const float* mask = (const float*)d_in[2];
    const float* pjw  = (const float*)d_in[3];
    const float* piw  = (const float*)d_in[4];
    const float* sw1  = (const float*)d_in[5];
    const float* sb1  = (const float*)d_in[6];
    const float* sw2  = (const float*)d_in[7];
    const float* sb2  = (const float*)d_in[8];
    const float* vw1  = (const float*)d_in[9];
    const float* vb1  = (const float*)d_in[10];
    const float* vw2  = (const float*)d_in[11];
    const float* vb2  = (const float*)d_in[12];
    const float* alpha= (const float*)d_in[13];
    float* out = (float*)d_out;

    void *pprobs, *pctx, *phid, *pp1, *pp2;
    cudaGetSymbolAddress(&pprobs, g_probs);
    cudaGetSymbolAddress(&pctx,   g_ctx);
    cudaGetSymbolAddress(&phid,   g_hid2);
    cudaGetSymbolAddress(&pp1,    g_part1);
    cudaGetSymbolAddress(&pp2,    g_part2);

    proj_kernel<<<NROWS, 256>>>(Hj, Hi, pjw, piw, sw1);
    pair_kernel<<<NROWS, 256>>>(sw1, sb1, sw2, sb2, mask);

    // ctx_b = probs_b (SxS) @ Hi_b (SxH)   [NN, batched over b]
    {
        dim3 g(Hh/128, Ss/128, Bb);
        gemm2_kernel<false,false,0,false><<<g, 256>>>(
            (const float*)pprobs, Hi, (float*)pctx, Hh, Ss, Hh, Ss,
            (long)Ss*Ss, (long)Ss*Hh, (long)Ss*Hh, nullptr, nullptr,
            nullptr, nullptr);
    }

    // part1 = msg_in @ v_w1^T   [NT, split-K=2, A fused from ctx/Hj]
    {
        dim3 g(OH/128, NROWS/128, 2);
        gemm2_kernel<true,true,0,true><<<g, 256>>>(
            nullptr, vw1, (float*)pp1, OH, H3, H3, H3/2,
            0, 0, (long)NROWS*OH, nullptr, nullptr,
            (const float*)pctx, Hj);
    }
    {
        long total = (long)NROWS*OH;
        reduce_kernel<true,false><<<(int)((total/4 + 255)/256), 256>>>(
            (const float*)pp1, (float*)phid, vb1, nullptr, OH, total);
    }

    // part2 = hid2 @ v_w2^T   [NT, split-K=2]
    {
        dim3 g(Hh/128, NROWS/128, 2);
        gemm2_kernel<true,true,0,false><<<g, 256>>>(
            (const float*)phid, vw2, (float*)pp2, Hh, OH, OH, OH/2,
            0, 0, (long)NROWS*Hh, nullptr, nullptr,
            nullptr, nullptr);
    }
    {
        long total = (long)NROWS*Hh;
        reduce_kernel<false,true><<<(int)((total/4 + 255)/256), 256>>>(
            (const float*)pp2, out, vb2, alpha, Hh, total);
    }
    (void)in_sizes; (void)n_in; (void)out_size;
}